// round 1
// baseline (speedup 1.0000x reference)
#include <cuda_runtime.h>
#include <cuda_bf16.h>
#include <math.h>

// ---------------------------------------------------------------------------
// Problem constants
// ---------------------------------------------------------------------------
#define LNUM 2
#define DMODEL 256
#define DFF 1024
#define NH 8
#define NP 4
#define CIN 512
#define BATCH 8
#define HH 64
#define WW 64
#define HW (HH * WW)            // 4096
#define MROWS (BATCH * HW)      // 32768
#define EPSV 1e-5f

// ---------------------------------------------------------------------------
// Scratch (device globals; no dynamic allocation allowed)
// ---------------------------------------------------------------------------
__device__ float g_XT[(size_t)MROWS * CIN];      // x transposed: (B*HW, CIN)  64MB
__device__ float g_SRC[(size_t)MROWS * DMODEL];  // src           32MB
__device__ float g_Q[(size_t)MROWS * DMODEL];    // q             32MB
__device__ float g_VAL[(size_t)MROWS * DMODEL];  // value         32MB
__device__ float g_T1[(size_t)MROWS * DMODEL];   // temp 256-wide 32MB
__device__ float g_OFF[(size_t)MROWS * NH * NP * 2]; // offsets   8MB
__device__ float g_ATT[(size_t)MROWS * NH * NP];     // attn      4MB
__device__ float g_H[(size_t)MROWS * DFF];       // big temp     128MB
__device__ float g_WIT[CIN * DMODEL];            // W_in^T
__device__ float g_WOT[DMODEL * CIN];            // W_out^T
__device__ float g_alpha1[DMODEL], g_beta1[DMODEL];
__device__ float g_alpha2[CIN],    g_beta2[CIN];

// ---------------------------------------------------------------------------
// Batched tiled transpose: in (batch, R, C) -> out (batch, C, R)
// grid: (C/32, R/32, batch), block (32, 8)
// ---------------------------------------------------------------------------
__global__ void transpose_kernel(const float* __restrict__ in, float* __restrict__ out,
                                 int R, int C)
{
    __shared__ float tile[32][33];
    size_t boff = (size_t)blockIdx.z * R * C;
    in += boff; out += boff;
    int c0 = blockIdx.x * 32;
    int r0 = blockIdx.y * 32;
    int x = threadIdx.x, y = threadIdx.y;
    #pragma unroll
    for (int j = 0; j < 32; j += 8)
        tile[y + j][x] = in[(size_t)(r0 + y + j) * C + c0 + x];
    __syncthreads();
    #pragma unroll
    for (int j = 0; j < 32; j += 8)
        out[(size_t)(c0 + y + j) * R + r0 + x] = tile[x][y + j];
}

// Transpose with BN scale/shift + ReLU applied per OUTPUT row (= channel).
// in (batch, R=HW, C=CIN) -> out (batch, CIN, HW)
__global__ void transpose_bn_relu_kernel(const float* __restrict__ in, float* __restrict__ out,
                                         const float* __restrict__ alpha,
                                         const float* __restrict__ beta,
                                         int R, int C)
{
    __shared__ float tile[32][33];
    size_t boff = (size_t)blockIdx.z * R * C;
    in += boff; out += boff;
    int c0 = blockIdx.x * 32;
    int r0 = blockIdx.y * 32;
    int x = threadIdx.x, y = threadIdx.y;
    #pragma unroll
    for (int j = 0; j < 32; j += 8)
        tile[y + j][x] = in[(size_t)(r0 + y + j) * C + c0 + x];
    __syncthreads();
    #pragma unroll
    for (int j = 0; j < 32; j += 8) {
        int ch = c0 + y + j;
        float v = tile[x][y + j] * alpha[ch] + beta[ch];
        out[(size_t)ch * R + r0 + x] = fmaxf(v, 0.0f);
    }
}

// ---------------------------------------------------------------------------
// BN param prep: alpha = g*rsqrt(v+eps), beta = b - m*alpha
// ---------------------------------------------------------------------------
__global__ void prep_bn_kernel(const float* g1, const float* b1, const float* m1, const float* v1,
                               const float* g2, const float* b2, const float* m2, const float* v2)
{
    int i = threadIdx.x + blockIdx.x * blockDim.x;
    if (i < DMODEL) {
        float a = g1[i] * rsqrtf(v1[i] + EPSV);
        g_alpha1[i] = a;
        g_beta1[i]  = b1[i] - m1[i] * a;
    }
    if (i < CIN) {
        float a = g2[i] * rsqrtf(v2[i] + EPSV);
        g_alpha2[i] = a;
        g_beta2[i]  = b2[i] - m2[i] * a;
    }
}

// ---------------------------------------------------------------------------
// Broadcast query embed (HW, D) -> Q (B, HW, D)
// ---------------------------------------------------------------------------
__global__ void bcast_q_kernel(const float* __restrict__ qe, float* __restrict__ Q)
{
    size_t i = (size_t)blockIdx.x * blockDim.x + threadIdx.x;
    size_t per = (size_t)HW * DMODEL;
    if (i < per) {
        float v = qe[i];
        #pragma unroll
        for (int b = 0; b < BATCH; b++)
            Q[(size_t)b * per + i] = v;
    }
}

// ---------------------------------------------------------------------------
// Generic tiled fp32 GEMM: C[M,N] = act((A[M,K] @ B[K,N]) * alpha[n] + beta[n])
// BM=64, BN=64, BK=16, 256 threads, 4x4 per thread.
// Requirements: M % 64 == 0, K % 16 == 0, N % 4 == 0.
// ---------------------------------------------------------------------------
__global__ void __launch_bounds__(256)
gemm_kernel(const float* __restrict__ A, const float* __restrict__ B,
            float* __restrict__ C, int M, int N, int K,
            const float* __restrict__ alpha, const float* __restrict__ beta,
            int do_relu)
{
    __shared__ float As[16][65];
    __shared__ float Bs[16][64];

    int bm = blockIdx.y * 64;
    int bn = blockIdx.x * 64;
    int t  = threadIdx.x;
    int tx = t & 15, ty = t >> 4;

    int arow = t >> 2;            // 0..63
    int acol = (t & 3) * 4;       // 0,4,8,12
    int brow = t >> 4;            // 0..15
    int bcol = (t & 15) * 4;      // 0..60

    float acc[4][4] = {};

    for (int k0 = 0; k0 < K; k0 += 16) {
        float4 av = *(const float4*)(A + (size_t)(bm + arow) * K + k0 + acol);
        As[acol + 0][arow] = av.x;
        As[acol + 1][arow] = av.y;
        As[acol + 2][arow] = av.z;
        As[acol + 3][arow] = av.w;
        float4 bv = make_float4(0.f, 0.f, 0.f, 0.f);
        if (bn + bcol < N)
            bv = *(const float4*)(B + (size_t)(k0 + brow) * N + bn + bcol);
        *(float4*)&Bs[brow][bcol] = bv;
        __syncthreads();
        #pragma unroll
        for (int kk = 0; kk < 16; kk++) {
            float a[4], b[4];
            #pragma unroll
            for (int j = 0; j < 4; j++) a[j] = As[kk][ty * 4 + j];
            float4 b4 = *(const float4*)&Bs[kk][tx * 4];
            b[0] = b4.x; b[1] = b4.y; b[2] = b4.z; b[3] = b4.w;
            #pragma unroll
            for (int i = 0; i < 4; i++)
                #pragma unroll
                for (int j = 0; j < 4; j++)
                    acc[i][j] = fmaf(a[i], b[j], acc[i][j]);
        }
        __syncthreads();
    }

    #pragma unroll
    for (int i = 0; i < 4; i++) {
        int row = bm + ty * 4 + i;
        #pragma unroll
        for (int j = 0; j < 4; j++) {
            int col = bn + tx * 4 + j;
            if (col < N) {
                float v = acc[i][j];
                float al = alpha ? alpha[col] : 1.0f;
                float be = beta  ? beta[col]  : 0.0f;
                v = v * al + be;
                if (do_relu) v = fmaxf(v, 0.0f);
                C[(size_t)row * N + col] = v;
            }
        }
    }
}

// ---------------------------------------------------------------------------
// Softmax over groups of NP=4 (attention weights)
// ---------------------------------------------------------------------------
__global__ void softmax4_kernel(float* __restrict__ ATT, int total)
{
    int i = blockIdx.x * blockDim.x + threadIdx.x;
    if (i >= total) return;
    float4 v = ((float4*)ATT)[i];
    float mx = fmaxf(fmaxf(v.x, v.y), fmaxf(v.z, v.w));
    float e0 = __expf(v.x - mx);
    float e1 = __expf(v.y - mx);
    float e2 = __expf(v.z - mx);
    float e3 = __expf(v.w - mx);
    float inv = 1.0f / (e0 + e1 + e2 + e3);
    ((float4*)ATT)[i] = make_float4(e0 * inv, e1 * inv, e2 * inv, e3 * inv);
}

// ---------------------------------------------------------------------------
// Deformable sampling: one block (256 threads) per query pixel.
// thread = output channel (head = t>>5). Writes O (M, 256).
// ---------------------------------------------------------------------------
__device__ __forceinline__ float fetch_val(const float* __restrict__ vb, int xi, int yi, int c)
{
    if (xi < 0 || xi >= WW || yi < 0 || yi >= HH) return 0.0f;
    return vb[((size_t)(yi * WW + xi)) * DMODEL + c];
}

__global__ void __launch_bounds__(256)
deform_sample_kernel(const float* __restrict__ VAL, const float* __restrict__ OFF,
                     const float* __restrict__ ATT, float* __restrict__ O)
{
    int m = blockIdx.x;                 // 0..MROWS-1
    int b = m >> 12;                    // /HW
    int pix = m & (HW - 1);
    int t = threadIdx.x;
    int head = t >> 5;
    int c = t;                          // channel = head*32 + lane

    float rx = ((pix & (WW - 1)) + 0.5f) * (1.0f / WW);
    float ry = ((pix >> 6) + 0.5f) * (1.0f / HH);

    const float* vb   = VAL + (size_t)b * HW * DMODEL;
    const float* offm = OFF + (size_t)m * (NH * NP * 2) + head * (NP * 2);
    const float* attm = ATT + (size_t)m * (NH * NP) + head * NP;

    float acc = 0.0f;
    #pragma unroll
    for (int p = 0; p < NP; p++) {
        float lx = rx + offm[p * 2 + 0] * (1.0f / WW);
        float ly = ry + offm[p * 2 + 1] * (1.0f / HH);
        float gx = lx * WW - 0.5f;
        float gy = ly * HH - 0.5f;
        float fx = floorf(gx), fy = floorf(gy);
        int x0 = (int)fx, y0 = (int)fy;
        float wx = gx - fx, wy = gy - fy;
        float v00 = fetch_val(vb, x0,     y0,     c);
        float v10 = fetch_val(vb, x0 + 1, y0,     c);
        float v01 = fetch_val(vb, x0,     y0 + 1, c);
        float v11 = fetch_val(vb, x0 + 1, y0 + 1, c);
        float s = v00 * (1.f - wx) * (1.f - wy) + v10 * wx * (1.f - wy)
                + v01 * (1.f - wx) * wy         + v11 * wx * wy;
        acc = fmaf(attm[p], s, acc);
    }
    O[(size_t)m * DMODEL + c] = acc;
}

// ---------------------------------------------------------------------------
// Residual + LayerNorm (in place on Q): Q = LN(Q + T, g, b). One warp per row.
// ---------------------------------------------------------------------------
__global__ void __launch_bounds__(256)
resid_ln_kernel(float* __restrict__ Q, const float* __restrict__ T,
                const float* __restrict__ gamma, const float* __restrict__ beta)
{
    int row  = blockIdx.x * 8 + (threadIdx.x >> 5);
    int lane = threadIdx.x & 31;
    const float4* qr = (const float4*)(Q + (size_t)row * DMODEL);
    const float4* tr = (const float4*)(T + (size_t)row * DMODEL);

    float x[8];
    float sum = 0.f, sumsq = 0.f;
    #pragma unroll
    for (int i = 0; i < 2; i++) {
        float4 a = qr[lane + i * 32];
        float4 b = tr[lane + i * 32];
        float v0 = a.x + b.x, v1 = a.y + b.y, v2 = a.z + b.z, v3 = a.w + b.w;
        x[i * 4 + 0] = v0; x[i * 4 + 1] = v1; x[i * 4 + 2] = v2; x[i * 4 + 3] = v3;
        sum += v0 + v1 + v2 + v3;
        sumsq += v0 * v0 + v1 * v1 + v2 * v2 + v3 * v3;
    }
    #pragma unroll
    for (int s = 16; s > 0; s >>= 1) {
        sum   += __shfl_xor_sync(0xffffffffu, sum, s);
        sumsq += __shfl_xor_sync(0xffffffffu, sumsq, s);
    }
    float mean = sum * (1.0f / DMODEL);
    float var  = sumsq * (1.0f / DMODEL) - mean * mean;
    float rstd = rsqrtf(var + EPSV);

    float4* qw = (float4*)(Q + (size_t)row * DMODEL);
    #pragma unroll
    for (int i = 0; i < 2; i++) {
        int e = (lane + i * 32) * 4;
        float4 o;
        o.x = (x[i * 4 + 0] - mean) * rstd * gamma[e + 0] + beta[e + 0];
        o.y = (x[i * 4 + 1] - mean) * rstd * gamma[e + 1] + beta[e + 1];
        o.z = (x[i * 4 + 2] - mean) * rstd * gamma[e + 2] + beta[e + 2];
        o.w = (x[i * 4 + 3] - mean) * rstd * gamma[e + 3] + beta[e + 3];
        qw[lane + i * 32] = o;
    }
}

// ---------------------------------------------------------------------------
// Launch
// ---------------------------------------------------------------------------
extern "C" void kernel_launch(void* const* d_in, const int* in_sizes, int n_in,
                              void* d_out, int out_size)
{
    const float* x      = (const float*)d_in[0];
    const float* W_in   = (const float*)d_in[1];
    const float* bn1_g  = (const float*)d_in[2];
    const float* bn1_b  = (const float*)d_in[3];
    const float* bn1_m  = (const float*)d_in[4];
    const float* bn1_v  = (const float*)d_in[5];
    const float* qembed = (const float*)d_in[6];
    const float* Woff   = (const float*)d_in[7];
    const float* boff   = (const float*)d_in[8];
    const float* Wattn  = (const float*)d_in[9];
    const float* battn  = (const float*)d_in[10];
    const float* Wval   = (const float*)d_in[11];
    const float* bval   = (const float*)d_in[12];
    const float* Wo     = (const float*)d_in[13];
    const float* bo     = (const float*)d_in[14];
    const float* ln1_g  = (const float*)d_in[15];
    const float* ln1_b  = (const float*)d_in[16];
    const float* W1     = (const float*)d_in[17];
    const float* b1     = (const float*)d_in[18];
    const float* W2     = (const float*)d_in[19];
    const float* b2     = (const float*)d_in[20];
    const float* ln2_g  = (const float*)d_in[21];
    const float* ln2_b  = (const float*)d_in[22];
    const float* W_out  = (const float*)d_in[23];
    const float* bn2_g  = (const float*)d_in[24];
    const float* bn2_b  = (const float*)d_in[25];
    const float* bn2_m  = (const float*)d_in[26];
    const float* bn2_v  = (const float*)d_in[27];
    float* out = (float*)d_out;

    float *XT, *SRC, *Q, *VAL, *T1, *OFF, *ATT, *H, *WIT, *WOT, *al1, *be1, *al2, *be2;
    cudaGetSymbolAddress((void**)&XT,  g_XT);
    cudaGetSymbolAddress((void**)&SRC, g_SRC);
    cudaGetSymbolAddress((void**)&Q,   g_Q);
    cudaGetSymbolAddress((void**)&VAL, g_VAL);
    cudaGetSymbolAddress((void**)&T1,  g_T1);
    cudaGetSymbolAddress((void**)&OFF, g_OFF);
    cudaGetSymbolAddress((void**)&ATT, g_ATT);
    cudaGetSymbolAddress((void**)&H,   g_H);
    cudaGetSymbolAddress((void**)&WIT, g_WIT);
    cudaGetSymbolAddress((void**)&WOT, g_WOT);
    cudaGetSymbolAddress((void**)&al1, g_alpha1);
    cudaGetSymbolAddress((void**)&be1, g_beta1);
    cudaGetSymbolAddress((void**)&al2, g_alpha2);
    cudaGetSymbolAddress((void**)&be2, g_beta2);

    dim3 tb32(32, 8);

    // x (B, CIN, HW) -> XT (B, HW, CIN)
    transpose_kernel<<<dim3(HW / 32, CIN / 32, BATCH), tb32>>>(x, XT, CIN, HW);
    // W_in (D, CIN) -> WIT (CIN, D)
    transpose_kernel<<<dim3(CIN / 32, DMODEL / 32, 1), tb32>>>(W_in, WIT, DMODEL, CIN);
    // W_out (CIN, D) -> WOT (D, CIN)
    transpose_kernel<<<dim3(DMODEL / 32, CIN / 32, 1), tb32>>>(W_out, WOT, CIN, DMODEL);

    prep_bn_kernel<<<1, 512>>>(bn1_g, bn1_b, bn1_m, bn1_v, bn2_g, bn2_b, bn2_m, bn2_v);

    // proj_in: SRC = relu((XT @ WIT) * alpha1 + beta1)
    gemm_kernel<<<dim3(DMODEL / 64, MROWS / 64), 256>>>(XT, WIT, SRC, MROWS, DMODEL, CIN,
                                                        al1, be1, 1);
    // Q = broadcast(query_embed)
    {
        int per = HW * DMODEL;
        bcast_q_kernel<<<(per + 255) / 256, 256>>>(qembed, Q);
    }

    for (int i = 0; i < LNUM; i++) {
        const float* Wval_i  = Wval  + (size_t)i * DMODEL * DMODEL;
        const float* bval_i  = bval  + (size_t)i * DMODEL;
        const float* Woff_i  = Woff  + (size_t)i * DMODEL * (NH * NP * 2);
        const float* boff_i  = boff  + (size_t)i * (NH * NP * 2);
        const float* Wattn_i = Wattn + (size_t)i * DMODEL * (NH * NP);
        const float* battn_i = battn + (size_t)i * (NH * NP);
        const float* Wo_i    = Wo    + (size_t)i * DMODEL * DMODEL;
        const float* bo_i    = bo    + (size_t)i * DMODEL;
        const float* W1_i    = W1    + (size_t)i * DMODEL * DFF;
        const float* b1_i    = b1    + (size_t)i * DFF;
        const float* W2_i    = W2    + (size_t)i * DFF * DMODEL;
        const float* b2_i    = b2    + (size_t)i * DMODEL;

        // value projection
        gemm_kernel<<<dim3(DMODEL / 64, MROWS / 64), 256>>>(SRC, Wval_i, VAL,
                                                            MROWS, DMODEL, DMODEL,
                                                            nullptr, bval_i, 0);
        // offsets + attention logits
        gemm_kernel<<<dim3(1, MROWS / 64), 256>>>(Q, Woff_i, OFF, MROWS, NH * NP * 2, DMODEL,
                                                  nullptr, boff_i, 0);
        gemm_kernel<<<dim3(1, MROWS / 64), 256>>>(Q, Wattn_i, ATT, MROWS, NH * NP, DMODEL,
                                                  nullptr, battn_i, 0);
        softmax4_kernel<<<(MROWS * NH + 255) / 256, 256>>>(ATT, MROWS * NH);

        // deformable sampling -> H (as M x 256)
        deform_sample_kernel<<<MROWS, 256>>>(VAL, OFF, ATT, H);

        // output projection
        gemm_kernel<<<dim3(DMODEL / 64, MROWS / 64), 256>>>(H, Wo_i, T1,
                                                            MROWS, DMODEL, DMODEL,
                                                            nullptr, bo_i, 0);
        // Q = LN(Q + T1)
        resid_ln_kernel<<<MROWS / 8, 256>>>(Q, T1, ln1_g + (size_t)i * DMODEL,
                                            ln1_b + (size_t)i * DMODEL);
        // FFN
        gemm_kernel<<<dim3(DFF / 64, MROWS / 64), 256>>>(Q, W1_i, H, MROWS, DFF, DMODEL,
                                                         nullptr, b1_i, 1);
        gemm_kernel<<<dim3(DMODEL / 64, MROWS / 64), 256>>>(H, W2_i, T1, MROWS, DMODEL, DFF,
                                                            nullptr, b2_i, 0);
        resid_ln_kernel<<<MROWS / 8, 256>>>(Q, T1, ln2_g + (size_t)i * DMODEL,
                                            ln2_b + (size_t)i * DMODEL);
    }

    // proj_out GEMM -> H (M x CIN), then transpose + BN + ReLU -> out (B, CIN, HW)
    gemm_kernel<<<dim3(CIN / 64, MROWS / 64), 256>>>(Q, WOT, H, MROWS, CIN, DMODEL,
                                                     nullptr, nullptr, 0);
    transpose_bn_relu_kernel<<<dim3(CIN / 32, HW / 32, BATCH), tb32>>>(H, out, al2, be2,
                                                                       HW, CIN);
}

// round 2
// speedup vs baseline: 2.5419x; 2.5419x over previous
#include <cuda_runtime.h>
#include <cuda_bf16.h>
#include <math.h>

// ---------------------------------------------------------------------------
// Problem constants
// ---------------------------------------------------------------------------
#define LNUM 2
#define DMODEL 256
#define DFF 1024
#define NH 8
#define NP 4
#define CIN 512
#define BATCH 8
#define HH 64
#define WW 64
#define HW (HH * WW)            // 4096
#define MROWS (BATCH * HW)      // 32768
#define EPSV 1e-5f

// ---------------------------------------------------------------------------
// Scratch (device globals; no dynamic allocation allowed)
// ---------------------------------------------------------------------------
__device__ float g_XT[(size_t)MROWS * CIN];      // x transposed: (B*HW, CIN)
__device__ float g_SRC[(size_t)MROWS * DMODEL];  // src
__device__ float g_Q[(size_t)MROWS * DMODEL];    // q
__device__ float g_VAL[(size_t)MROWS * DMODEL];  // value
__device__ float g_T1[(size_t)MROWS * DMODEL];   // temp 256-wide
__device__ float g_OFF[(size_t)MROWS * NH * NP * 2]; // offsets
__device__ float g_ATT[(size_t)MROWS * NH * NP];     // attn
__device__ float g_H[(size_t)MROWS * DFF];       // big temp
__device__ float g_WIT[CIN * DMODEL];            // W_in^T
__device__ float g_WOT[DMODEL * CIN];            // W_out^T
__device__ float g_alpha1[DMODEL], g_beta1[DMODEL];
__device__ float g_alpha2[CIN],    g_beta2[CIN];

// ---------------------------------------------------------------------------
// tf32 conversion (round-to-nearest; avoids truncation bias)
// ---------------------------------------------------------------------------
__device__ __forceinline__ unsigned f2tf(float f)
{
    unsigned r;
    asm("cvt.rna.tf32.f32 %0, %1;" : "=r"(r) : "f"(f));
    return r;
}

// ---------------------------------------------------------------------------
// TF32 tensor-core GEMM:
//   C[M,N] = act((A[M,K] @ B[K,N]) * alpha[n] + beta[n])
// Block tile 128x128, BK=16, 8 warps (warp tile 64x32), mma.m16n8k8.
// Requirements: M % 128 == 0, K % 16 == 0. N arbitrary multiple of 2.
// ---------------------------------------------------------------------------
__global__ void __launch_bounds__(256)
gemm_tf32_kernel(const float* __restrict__ A, const float* __restrict__ B,
                 float* __restrict__ C, int M, int N, int K,
                 const float* __restrict__ alpha, const float* __restrict__ beta,
                 int do_relu)
{
    // padded strides chosen for conflict-free fragment LDS
    __shared__ unsigned As[128][20];   // [m][k], stride 20
    __shared__ unsigned Bs[16][136];   // [k][n], stride 136

    const int t    = threadIdx.x;
    const int bm   = blockIdx.y * 128;
    const int bn   = blockIdx.x * 128;
    const int warp = t >> 5;
    const int lane = t & 31;
    const int wm   = (warp & 1) * 64;   // 2 warps along M
    const int wn   = (warp >> 1) * 32;  // 4 warps along N
    const int gid  = lane >> 2;
    const int q    = lane & 3;

    // global-load register staging
    float4 ar[2], br[2];
    const int a_r = t >> 2;        // 0..63 (+64 for i=1)
    const int a_c = (t & 3) * 4;
    const int b_r = t >> 5;        // 0..7 (+8 for i=1)
    const int b_c = (t & 31) * 4;

    float acc[4][4][4];
    #pragma unroll
    for (int mi = 0; mi < 4; mi++)
        #pragma unroll
        for (int ni = 0; ni < 4; ni++)
            #pragma unroll
            for (int r = 0; r < 4; r++) acc[mi][ni][r] = 0.0f;

    const int nk = K >> 4;

    // ---- prologue: load chunk 0 ----
    #pragma unroll
    for (int i = 0; i < 2; i++) {
        ar[i] = *(const float4*)(A + (size_t)(bm + a_r + i * 64) * K + a_c);
        br[i] = (bn + b_c < N)
              ? *(const float4*)(B + (size_t)(b_r + i * 8) * N + bn + b_c)
              : make_float4(0.f, 0.f, 0.f, 0.f);
    }
    #pragma unroll
    for (int i = 0; i < 2; i++) {
        int r = a_r + i * 64;
        As[r][a_c + 0] = f2tf(ar[i].x);
        As[r][a_c + 1] = f2tf(ar[i].y);
        As[r][a_c + 2] = f2tf(ar[i].z);
        As[r][a_c + 3] = f2tf(ar[i].w);
        int rb = b_r + i * 8;
        Bs[rb][b_c + 0] = f2tf(br[i].x);
        Bs[rb][b_c + 1] = f2tf(br[i].y);
        Bs[rb][b_c + 2] = f2tf(br[i].z);
        Bs[rb][b_c + 3] = f2tf(br[i].w);
    }
    __syncthreads();

    for (int kc = 0; kc < nk; kc++) {
        // issue next chunk's global loads (latency hidden behind compute)
        if (kc + 1 < nk) {
            int k0 = (kc + 1) << 4;
            #pragma unroll
            for (int i = 0; i < 2; i++) {
                ar[i] = *(const float4*)(A + (size_t)(bm + a_r + i * 64) * K + k0 + a_c);
                br[i] = (bn + b_c < N)
                      ? *(const float4*)(B + (size_t)(k0 + b_r + i * 8) * N + bn + b_c)
                      : make_float4(0.f, 0.f, 0.f, 0.f);
            }
        }

        // compute: 2 k-steps of 8
        #pragma unroll
        for (int ks = 0; ks < 2; ks++) {
            const int k = ks * 8;
            unsigned af[4][4], bf[4][2];
            #pragma unroll
            for (int mi = 0; mi < 4; mi++) {
                int m0 = wm + mi * 16;
                af[mi][0] = As[m0 + gid    ][k + q];
                af[mi][1] = As[m0 + gid + 8][k + q];
                af[mi][2] = As[m0 + gid    ][k + q + 4];
                af[mi][3] = As[m0 + gid + 8][k + q + 4];
            }
            #pragma unroll
            for (int ni = 0; ni < 4; ni++) {
                int n0 = wn + ni * 8 + gid;
                bf[ni][0] = Bs[k + q    ][n0];
                bf[ni][1] = Bs[k + q + 4][n0];
            }
            #pragma unroll
            for (int mi = 0; mi < 4; mi++)
                #pragma unroll
                for (int ni = 0; ni < 4; ni++) {
                    asm volatile(
                        "mma.sync.aligned.m16n8k8.row.col.f32.tf32.tf32.f32 "
                        "{%0,%1,%2,%3}, {%4,%5,%6,%7}, {%8,%9}, {%0,%1,%2,%3};\n"
                        : "+f"(acc[mi][ni][0]), "+f"(acc[mi][ni][1]),
                          "+f"(acc[mi][ni][2]), "+f"(acc[mi][ni][3])
                        : "r"(af[mi][0]), "r"(af[mi][1]), "r"(af[mi][2]), "r"(af[mi][3]),
                          "r"(bf[ni][0]), "r"(bf[ni][1]));
                }
        }
        __syncthreads();

        if (kc + 1 < nk) {
            #pragma unroll
            for (int i = 0; i < 2; i++) {
                int r = a_r + i * 64;
                As[r][a_c + 0] = f2tf(ar[i].x);
                As[r][a_c + 1] = f2tf(ar[i].y);
                As[r][a_c + 2] = f2tf(ar[i].z);
                As[r][a_c + 3] = f2tf(ar[i].w);
                int rb = b_r + i * 8;
                Bs[rb][b_c + 0] = f2tf(br[i].x);
                Bs[rb][b_c + 1] = f2tf(br[i].y);
                Bs[rb][b_c + 2] = f2tf(br[i].z);
                Bs[rb][b_c + 3] = f2tf(br[i].w);
            }
            __syncthreads();
        }
    }

    // ---- epilogue ----
    #pragma unroll
    for (int mi = 0; mi < 4; mi++) {
        #pragma unroll
        for (int ni = 0; ni < 4; ni++) {
            int col = bn + wn + ni * 8 + 2 * q;
            if (col >= N) continue;
            float al0 = alpha ? alpha[col]     : 1.0f;
            float al1 = alpha ? alpha[col + 1] : 1.0f;
            float be0 = beta  ? beta[col]      : 0.0f;
            float be1 = beta  ? beta[col + 1]  : 0.0f;
            #pragma unroll
            for (int h = 0; h < 2; h++) {
                int row = bm + wm + mi * 16 + gid + h * 8;
                float v0 = acc[mi][ni][2 * h + 0] * al0 + be0;
                float v1 = acc[mi][ni][2 * h + 1] * al1 + be1;
                if (do_relu) { v0 = fmaxf(v0, 0.f); v1 = fmaxf(v1, 0.f); }
                *(float2*)(C + (size_t)row * N + col) = make_float2(v0, v1);
            }
        }
    }
}

// ---------------------------------------------------------------------------
// Batched tiled transpose: in (batch, R, C) -> out (batch, C, R)
// ---------------------------------------------------------------------------
__global__ void transpose_kernel(const float* __restrict__ in, float* __restrict__ out,
                                 int R, int C)
{
    __shared__ float tile[32][33];
    size_t boff = (size_t)blockIdx.z * R * C;
    in += boff; out += boff;
    int c0 = blockIdx.x * 32;
    int r0 = blockIdx.y * 32;
    int x = threadIdx.x, y = threadIdx.y;
    #pragma unroll
    for (int j = 0; j < 32; j += 8)
        tile[y + j][x] = in[(size_t)(r0 + y + j) * C + c0 + x];
    __syncthreads();
    #pragma unroll
    for (int j = 0; j < 32; j += 8)
        out[(size_t)(c0 + y + j) * R + r0 + x] = tile[x][y + j];
}

__global__ void transpose_bn_relu_kernel(const float* __restrict__ in, float* __restrict__ out,
                                         const float* __restrict__ alpha,
                                         const float* __restrict__ beta,
                                         int R, int C)
{
    __shared__ float tile[32][33];
    size_t boff = (size_t)blockIdx.z * R * C;
    in += boff; out += boff;
    int c0 = blockIdx.x * 32;
    int r0 = blockIdx.y * 32;
    int x = threadIdx.x, y = threadIdx.y;
    #pragma unroll
    for (int j = 0; j < 32; j += 8)
        tile[y + j][x] = in[(size_t)(r0 + y + j) * C + c0 + x];
    __syncthreads();
    #pragma unroll
    for (int j = 0; j < 32; j += 8) {
        int ch = c0 + y + j;
        float v = tile[x][y + j] * alpha[ch] + beta[ch];
        out[(size_t)ch * R + r0 + x] = fmaxf(v, 0.0f);
    }
}

__global__ void prep_bn_kernel(const float* g1, const float* b1, const float* m1, const float* v1,
                               const float* g2, const float* b2, const float* m2, const float* v2)
{
    int i = threadIdx.x + blockIdx.x * blockDim.x;
    if (i < DMODEL) {
        float a = g1[i] * rsqrtf(v1[i] + EPSV);
        g_alpha1[i] = a;
        g_beta1[i]  = b1[i] - m1[i] * a;
    }
    if (i < CIN) {
        float a = g2[i] * rsqrtf(v2[i] + EPSV);
        g_alpha2[i] = a;
        g_beta2[i]  = b2[i] - m2[i] * a;
    }
}

__global__ void bcast_q_kernel(const float* __restrict__ qe, float* __restrict__ Q)
{
    size_t i = (size_t)blockIdx.x * blockDim.x + threadIdx.x;
    size_t per = (size_t)HW * DMODEL;
    if (i < per) {
        float v = qe[i];
        #pragma unroll
        for (int b = 0; b < BATCH; b++)
            Q[(size_t)b * per + i] = v;
    }
}

__global__ void softmax4_kernel(float* __restrict__ ATT, int total)
{
    int i = blockIdx.x * blockDim.x + threadIdx.x;
    if (i >= total) return;
    float4 v = ((float4*)ATT)[i];
    float mx = fmaxf(fmaxf(v.x, v.y), fmaxf(v.z, v.w));
    float e0 = __expf(v.x - mx);
    float e1 = __expf(v.y - mx);
    float e2 = __expf(v.z - mx);
    float e3 = __expf(v.w - mx);
    float inv = 1.0f / (e0 + e1 + e2 + e3);
    ((float4*)ATT)[i] = make_float4(e0 * inv, e1 * inv, e2 * inv, e3 * inv);
}

// ---------------------------------------------------------------------------
// Deformable sampling
// ---------------------------------------------------------------------------
__device__ __forceinline__ float fetch_val(const float* __restrict__ vb, int xi, int yi, int c)
{
    if (xi < 0 || xi >= WW || yi < 0 || yi >= HH) return 0.0f;
    return vb[((size_t)(yi * WW + xi)) * DMODEL + c];
}

__global__ void __launch_bounds__(256)
deform_sample_kernel(const float* __restrict__ VAL, const float* __restrict__ OFF,
                     const float* __restrict__ ATT, float* __restrict__ O)
{
    int m = blockIdx.x;
    int b = m >> 12;
    int pix = m & (HW - 1);
    int t = threadIdx.x;
    int head = t >> 5;
    int c = t;

    float rx = ((pix & (WW - 1)) + 0.5f) * (1.0f / WW);
    float ry = ((pix >> 6) + 0.5f) * (1.0f / HH);

    const float* vb   = VAL + (size_t)b * HW * DMODEL;
    const float* offm = OFF + (size_t)m * (NH * NP * 2) + head * (NP * 2);
    const float* attm = ATT + (size_t)m * (NH * NP) + head * NP;

    float acc = 0.0f;
    #pragma unroll
    for (int p = 0; p < NP; p++) {
        float lx = rx + offm[p * 2 + 0] * (1.0f / WW);
        float ly = ry + offm[p * 2 + 1] * (1.0f / HH);
        float gx = lx * WW - 0.5f;
        float gy = ly * HH - 0.5f;
        float fx = floorf(gx), fy = floorf(gy);
        int x0 = (int)fx, y0 = (int)fy;
        float wx = gx - fx, wy = gy - fy;
        float v00 = fetch_val(vb, x0,     y0,     c);
        float v10 = fetch_val(vb, x0 + 1, y0,     c);
        float v01 = fetch_val(vb, x0,     y0 + 1, c);
        float v11 = fetch_val(vb, x0 + 1, y0 + 1, c);
        float s = v00 * (1.f - wx) * (1.f - wy) + v10 * wx * (1.f - wy)
                + v01 * (1.f - wx) * wy         + v11 * wx * wy;
        acc = fmaf(attm[p], s, acc);
    }
    O[(size_t)m * DMODEL + c] = acc;
}

// ---------------------------------------------------------------------------
// Residual + LayerNorm (in place on Q)
// ---------------------------------------------------------------------------
__global__ void __launch_bounds__(256)
resid_ln_kernel(float* __restrict__ Q, const float* __restrict__ T,
                const float* __restrict__ gamma, const float* __restrict__ beta)
{
    int row  = blockIdx.x * 8 + (threadIdx.x >> 5);
    int lane = threadIdx.x & 31;
    const float4* qr = (const float4*)(Q + (size_t)row * DMODEL);
    const float4* tr = (const float4*)(T + (size_t)row * DMODEL);

    float x[8];
    float sum = 0.f, sumsq = 0.f;
    #pragma unroll
    for (int i = 0; i < 2; i++) {
        float4 a = qr[lane + i * 32];
        float4 b = tr[lane + i * 32];
        float v0 = a.x + b.x, v1 = a.y + b.y, v2 = a.z + b.z, v3 = a.w + b.w;
        x[i * 4 + 0] = v0; x[i * 4 + 1] = v1; x[i * 4 + 2] = v2; x[i * 4 + 3] = v3;
        sum += v0 + v1 + v2 + v3;
        sumsq += v0 * v0 + v1 * v1 + v2 * v2 + v3 * v3;
    }
    #pragma unroll
    for (int s = 16; s > 0; s >>= 1) {
        sum   += __shfl_xor_sync(0xffffffffu, sum, s);
        sumsq += __shfl_xor_sync(0xffffffffu, sumsq, s);
    }
    float mean = sum * (1.0f / DMODEL);
    float var  = sumsq * (1.0f / DMODEL) - mean * mean;
    float rstd = rsqrtf(var + EPSV);

    float4* qw = (float4*)(Q + (size_t)row * DMODEL);
    #pragma unroll
    for (int i = 0; i < 2; i++) {
        int e = (lane + i * 32) * 4;
        float4 o;
        o.x = (x[i * 4 + 0] - mean) * rstd * gamma[e + 0] + beta[e + 0];
        o.y = (x[i * 4 + 1] - mean) * rstd * gamma[e + 1] + beta[e + 1];
        o.z = (x[i * 4 + 2] - mean) * rstd * gamma[e + 2] + beta[e + 2];
        o.w = (x[i * 4 + 3] - mean) * rstd * gamma[e + 3] + beta[e + 3];
        qw[lane + i * 32] = o;
    }
}

// ---------------------------------------------------------------------------
// Launch
// ---------------------------------------------------------------------------
extern "C" void kernel_launch(void* const* d_in, const int* in_sizes, int n_in,
                              void* d_out, int out_size)
{
    const float* x      = (const float*)d_in[0];
    const float* W_in   = (const float*)d_in[1];
    const float* bn1_g  = (const float*)d_in[2];
    const float* bn1_b  = (const float*)d_in[3];
    const float* bn1_m  = (const float*)d_in[4];
    const float* bn1_v  = (const float*)d_in[5];
    const float* qembed = (const float*)d_in[6];
    const float* Woff   = (const float*)d_in[7];
    const float* boff   = (const float*)d_in[8];
    const float* Wattn  = (const float*)d_in[9];
    const float* battn  = (const float*)d_in[10];
    const float* Wval   = (const float*)d_in[11];
    const float* bval   = (const float*)d_in[12];
    const float* Wo     = (const float*)d_in[13];
    const float* bo     = (const float*)d_in[14];
    const float* ln1_g  = (const float*)d_in[15];
    const float* ln1_b  = (const float*)d_in[16];
    const float* W1     = (const float*)d_in[17];
    const float* b1     = (const float*)d_in[18];
    const float* W2     = (const float*)d_in[19];
    const float* b2     = (const float*)d_in[20];
    const float* ln2_g  = (const float*)d_in[21];
    const float* ln2_b  = (const float*)d_in[22];
    const float* W_out  = (const float*)d_in[23];
    const float* bn2_g  = (const float*)d_in[24];
    const float* bn2_b  = (const float*)d_in[25];
    const float* bn2_m  = (const float*)d_in[26];
    const float* bn2_v  = (const float*)d_in[27];
    float* out = (float*)d_out;

    float *XT, *SRC, *Q, *VAL, *T1, *OFF, *ATT, *H, *WIT, *WOT, *al1, *be1, *al2, *be2;
    cudaGetSymbolAddress((void**)&XT,  g_XT);
    cudaGetSymbolAddress((void**)&SRC, g_SRC);
    cudaGetSymbolAddress((void**)&Q,   g_Q);
    cudaGetSymbolAddress((void**)&VAL, g_VAL);
    cudaGetSymbolAddress((void**)&T1,  g_T1);
    cudaGetSymbolAddress((void**)&OFF, g_OFF);
    cudaGetSymbolAddress((void**)&ATT, g_ATT);
    cudaGetSymbolAddress((void**)&H,   g_H);
    cudaGetSymbolAddress((void**)&WIT, g_WIT);
    cudaGetSymbolAddress((void**)&WOT, g_WOT);
    cudaGetSymbolAddress((void**)&al1, g_alpha1);
    cudaGetSymbolAddress((void**)&be1, g_beta1);
    cudaGetSymbolAddress((void**)&al2, g_alpha2);
    cudaGetSymbolAddress((void**)&be2, g_beta2);

    dim3 tb32(32, 8);

    transpose_kernel<<<dim3(HW / 32, CIN / 32, BATCH), tb32>>>(x, XT, CIN, HW);
    transpose_kernel<<<dim3(CIN / 32, DMODEL / 32, 1), tb32>>>(W_in, WIT, DMODEL, CIN);
    transpose_kernel<<<dim3(DMODEL / 32, CIN / 32, 1), tb32>>>(W_out, WOT, CIN, DMODEL);

    prep_bn_kernel<<<1, 512>>>(bn1_g, bn1_b, bn1_m, bn1_v, bn2_g, bn2_b, bn2_m, bn2_v);

    // proj_in: SRC = relu((XT @ WIT) * alpha1 + beta1)
    gemm_tf32_kernel<<<dim3(DMODEL / 128, MROWS / 128), 256>>>(XT, WIT, SRC,
                                                               MROWS, DMODEL, CIN,
                                                               al1, be1, 1);
    {
        int per = HW * DMODEL;
        bcast_q_kernel<<<(per + 255) / 256, 256>>>(qembed, Q);
    }

    for (int i = 0; i < LNUM; i++) {
        const float* Wval_i  = Wval  + (size_t)i * DMODEL * DMODEL;
        const float* bval_i  = bval  + (size_t)i * DMODEL;
        const float* Woff_i  = Woff  + (size_t)i * DMODEL * (NH * NP * 2);
        const float* boff_i  = boff  + (size_t)i * (NH * NP * 2);
        const float* Wattn_i = Wattn + (size_t)i * DMODEL * (NH * NP);
        const float* battn_i = battn + (size_t)i * (NH * NP);
        const float* Wo_i    = Wo    + (size_t)i * DMODEL * DMODEL;
        const float* bo_i    = bo    + (size_t)i * DMODEL;
        const float* W1_i    = W1    + (size_t)i * DMODEL * DFF;
        const float* b1_i    = b1    + (size_t)i * DFF;
        const float* W2_i    = W2    + (size_t)i * DFF * DMODEL;
        const float* b2_i    = b2    + (size_t)i * DMODEL;

        gemm_tf32_kernel<<<dim3(DMODEL / 128, MROWS / 128), 256>>>(SRC, Wval_i, VAL,
                                                                   MROWS, DMODEL, DMODEL,
                                                                   nullptr, bval_i, 0);
        gemm_tf32_kernel<<<dim3(1, MROWS / 128), 256>>>(Q, Woff_i, OFF,
                                                        MROWS, NH * NP * 2, DMODEL,
                                                        nullptr, boff_i, 0);
        gemm_tf32_kernel<<<dim3(1, MROWS / 128), 256>>>(Q, Wattn_i, ATT,
                                                        MROWS, NH * NP, DMODEL,
                                                        nullptr, battn_i, 0);
        softmax4_kernel<<<(MROWS * NH + 255) / 256, 256>>>(ATT, MROWS * NH);

        deform_sample_kernel<<<MROWS, 256>>>(VAL, OFF, ATT, H);

        gemm_tf32_kernel<<<dim3(DMODEL / 128, MROWS / 128), 256>>>(H, Wo_i, T1,
                                                                   MROWS, DMODEL, DMODEL,
                                                                   nullptr, bo_i, 0);
        resid_ln_kernel<<<MROWS / 8, 256>>>(Q, T1, ln1_g + (size_t)i * DMODEL,
                                            ln1_b + (size_t)i * DMODEL);
        gemm_tf32_kernel<<<dim3(DFF / 128, MROWS / 128), 256>>>(Q, W1_i, H,
                                                                MROWS, DFF, DMODEL,
                                                                nullptr, b1_i, 1);
        gemm_tf32_kernel<<<dim3(DMODEL / 128, MROWS / 128), 256>>>(H, W2_i, T1,
                                                                   MROWS, DMODEL, DFF,
                                                                   nullptr, b2_i, 0);
        resid_ln_kernel<<<MROWS / 8, 256>>>(Q, T1, ln2_g + (size_t)i * DMODEL,
                                            ln2_b + (size_t)i * DMODEL);
    }

    gemm_tf32_kernel<<<dim3(CIN / 128, MROWS / 128), 256>>>(Q, WOT, H,
                                                            MROWS, CIN, DMODEL,
                                                            nullptr, nullptr, 0);
    transpose_bn_relu_kernel<<<dim3(CIN / 32, HW / 32, BATCH), tb32>>>(H, out, al2, be2,
                                                                       HW, CIN);
}

// round 6
// speedup vs baseline: 2.5987x; 1.0224x over previous
#include <cuda_runtime.h>
#include <cuda_bf16.h>
#include <math.h>

// ---------------------------------------------------------------------------
// Problem constants
// ---------------------------------------------------------------------------
#define LNUM 2
#define DMODEL 256
#define DFF 1024
#define NH 8
#define NP 4
#define CIN 512
#define BATCH 8
#define HH 64
#define WW 64
#define HW (HH * WW)            // 4096
#define MROWS (BATCH * HW)      // 32768
#define EPSV 1e-5f
#define NOA 96                  // merged offsets(64) + attn(32) width

// ---------------------------------------------------------------------------
// Scratch (device globals; no dynamic allocation allowed)
// ---------------------------------------------------------------------------
__device__ float g_XT[(size_t)MROWS * CIN];
__device__ float g_SRC[(size_t)MROWS * DMODEL];
__device__ float g_Q[(size_t)MROWS * DMODEL];
__device__ float g_VAL[(size_t)MROWS * DMODEL];
__device__ float g_T1[(size_t)MROWS * DMODEL];
__device__ float g_OA[(size_t)MROWS * NOA];      // merged offsets+attn logits
__device__ float g_H[(size_t)MROWS * DFF];
__device__ float g_WIT[CIN * DMODEL];
__device__ float g_WOT[DMODEL * CIN];
__device__ float g_WOA[DMODEL * NOA];
__device__ float g_bOA[NOA];
__device__ float g_alpha1[DMODEL], g_beta1[DMODEL];
__device__ float g_alpha2[CIN],    g_beta2[CIN];

// ---------------------------------------------------------------------------
// tf32 conversion (round-to-nearest)
// ---------------------------------------------------------------------------
__device__ __forceinline__ unsigned f2tf(float f)
{
    unsigned r;
    asm("cvt.rna.tf32.f32 %0, %1;" : "=r"(r) : "f"(f));
    return r;
}

// ---------------------------------------------------------------------------
// TF32 tensor-core GEMM, double-buffered smem.
//   C[M,N] = act((A[M,K] @ B[K,N]) * alpha[n] + beta[n])
// Block tile 128x128, BK=16, 8 warps (warp tile 64x32), mma.m16n8k8.
// M % 128 == 0, K % 16 == 0, N % 2 == 0 (cols >= N masked out).
// ---------------------------------------------------------------------------
__global__ void __launch_bounds__(256)
gemm_tf32_kernel(const float* __restrict__ A, const float* __restrict__ B,
                 float* __restrict__ C, int M, int N, int K,
                 const float* __restrict__ alpha, const float* __restrict__ beta,
                 int do_relu)
{
    __shared__ unsigned As[2][128][20];   // [buf][m][k]
    __shared__ unsigned Bs[2][16][136];   // [buf][k][n]

    const int t    = threadIdx.x;
    const int bm   = blockIdx.y * 128;
    const int bn   = blockIdx.x * 128;
    const int warp = t >> 5;
    const int lane = t & 31;
    const int wm   = (warp & 1) * 64;
    const int wn   = (warp >> 1) * 32;
    const int gid  = lane >> 2;
    const int q    = lane & 3;

    float4 ar[2], br[2];
    const int a_r = t >> 2;
    const int a_c = (t & 3) * 4;
    const int b_r = t >> 5;
    const int b_c = (t & 31) * 4;

    float acc[4][4][4];
    #pragma unroll
    for (int mi = 0; mi < 4; mi++)
        #pragma unroll
        for (int ni = 0; ni < 4; ni++)
            #pragma unroll
            for (int r = 0; r < 4; r++) acc[mi][ni][r] = 0.0f;

    const int nk = K >> 4;

    // prologue: chunk 0 -> buf 0
    #pragma unroll
    for (int i = 0; i < 2; i++) {
        ar[i] = *(const float4*)(A + (size_t)(bm + a_r + i * 64) * K + a_c);
        br[i] = (bn + b_c < N)
              ? *(const float4*)(B + (size_t)(b_r + i * 8) * N + bn + b_c)
              : make_float4(0.f, 0.f, 0.f, 0.f);
    }
    #pragma unroll
    for (int i = 0; i < 2; i++) {
        int r = a_r + i * 64;
        As[0][r][a_c + 0] = f2tf(ar[i].x);
        As[0][r][a_c + 1] = f2tf(ar[i].y);
        As[0][r][a_c + 2] = f2tf(ar[i].z);
        As[0][r][a_c + 3] = f2tf(ar[i].w);
        int rb = b_r + i * 8;
        Bs[0][rb][b_c + 0] = f2tf(br[i].x);
        Bs[0][rb][b_c + 1] = f2tf(br[i].y);
        Bs[0][rb][b_c + 2] = f2tf(br[i].z);
        Bs[0][rb][b_c + 3] = f2tf(br[i].w);
    }
    __syncthreads();

    for (int kc = 0; kc < nk; kc++) {
        const int cur = kc & 1;
        const int nxt = cur ^ 1;
        if (kc + 1 < nk) {
            int k0 = (kc + 1) << 4;
            #pragma unroll
            for (int i = 0; i < 2; i++) {
                ar[i] = *(const float4*)(A + (size_t)(bm + a_r + i * 64) * K + k0 + a_c);
                br[i] = (bn + b_c < N)
                      ? *(const float4*)(B + (size_t)(k0 + b_r + i * 8) * N + bn + b_c)
                      : make_float4(0.f, 0.f, 0.f, 0.f);
            }
        }

        #pragma unroll
        for (int ks = 0; ks < 2; ks++) {
            const int k = ks * 8;
            unsigned af[4][4], bf[4][2];
            #pragma unroll
            for (int mi = 0; mi < 4; mi++) {
                int m0 = wm + mi * 16;
                af[mi][0] = As[cur][m0 + gid    ][k + q];
                af[mi][1] = As[cur][m0 + gid + 8][k + q];
                af[mi][2] = As[cur][m0 + gid    ][k + q + 4];
                af[mi][3] = As[cur][m0 + gid + 8][k + q + 4];
            }
            #pragma unroll
            for (int ni = 0; ni < 4; ni++) {
                int n0 = wn + ni * 8 + gid;
                bf[ni][0] = Bs[cur][k + q    ][n0];
                bf[ni][1] = Bs[cur][k + q + 4][n0];
            }
            #pragma unroll
            for (int mi = 0; mi < 4; mi++)
                #pragma unroll
                for (int ni = 0; ni < 4; ni++) {
                    asm volatile(
                        "mma.sync.aligned.m16n8k8.row.col.f32.tf32.tf32.f32 "
                        "{%0,%1,%2,%3}, {%4,%5,%6,%7}, {%8,%9}, {%0,%1,%2,%3};\n"
                        : "+f"(acc[mi][ni][0]), "+f"(acc[mi][ni][1]),
                          "+f"(acc[mi][ni][2]), "+f"(acc[mi][ni][3])
                        : "r"(af[mi][0]), "r"(af[mi][1]), "r"(af[mi][2]), "r"(af[mi][3]),
                          "r"(bf[ni][0]), "r"(bf[ni][1]));
                }
        }

        if (kc + 1 < nk) {
            #pragma unroll
            for (int i = 0; i < 2; i++) {
                int r = a_r + i * 64;
                As[nxt][r][a_c + 0] = f2tf(ar[i].x);
                As[nxt][r][a_c + 1] = f2tf(ar[i].y);
                As[nxt][r][a_c + 2] = f2tf(ar[i].z);
                As[nxt][r][a_c + 3] = f2tf(ar[i].w);
                int rb = b_r + i * 8;
                Bs[nxt][rb][b_c + 0] = f2tf(br[i].x);
                Bs[nxt][rb][b_c + 1] = f2tf(br[i].y);
                Bs[nxt][rb][b_c + 2] = f2tf(br[i].z);
                Bs[nxt][rb][b_c + 3] = f2tf(br[i].w);
            }
            __syncthreads();
        }
    }

    // epilogue
    #pragma unroll
    for (int mi = 0; mi < 4; mi++) {
        #pragma unroll
        for (int ni = 0; ni < 4; ni++) {
            int col = bn + wn + ni * 8 + 2 * q;
            if (col >= N) continue;
            float al0 = alpha ? alpha[col]     : 1.0f;
            float al1 = alpha ? alpha[col + 1] : 1.0f;
            float be0 = beta  ? beta[col]      : 0.0f;
            float be1 = beta  ? beta[col + 1]  : 0.0f;
            #pragma unroll
            for (int h = 0; h < 2; h++) {
                int row = bm + wm + mi * 16 + gid + h * 8;
                float v0 = acc[mi][ni][2 * h + 0] * al0 + be0;
                float v1 = acc[mi][ni][2 * h + 1] * al1 + be1;
                if (do_relu) { v0 = fmaxf(v0, 0.f); v1 = fmaxf(v1, 0.f); }
                *(float2*)(C + (size_t)row * N + col) = make_float2(v0, v1);
            }
        }
    }
}

// ---------------------------------------------------------------------------
// Transposes
// ---------------------------------------------------------------------------
__global__ void transpose_kernel(const float* __restrict__ in, float* __restrict__ out,
                                 int R, int C)
{
    __shared__ float tile[32][33];
    size_t boff = (size_t)blockIdx.z * R * C;
    in += boff; out += boff;
    int c0 = blockIdx.x * 32;
    int r0 = blockIdx.y * 32;
    int x = threadIdx.x, y = threadIdx.y;
    #pragma unroll
    for (int j = 0; j < 32; j += 8)
        tile[y + j][x] = in[(size_t)(r0 + y + j) * C + c0 + x];
    __syncthreads();
    #pragma unroll
    for (int j = 0; j < 32; j += 8)
        out[(size_t)(c0 + y + j) * R + r0 + x] = tile[x][y + j];
}

__global__ void transpose_bn_relu_kernel(const float* __restrict__ in, float* __restrict__ out,
                                         const float* __restrict__ alpha,
                                         const float* __restrict__ beta,
                                         int R, int C)
{
    __shared__ float tile[32][33];
    size_t boff = (size_t)blockIdx.z * R * C;
    in += boff; out += boff;
    int c0 = blockIdx.x * 32;
    int r0 = blockIdx.y * 32;
    int x = threadIdx.x, y = threadIdx.y;
    #pragma unroll
    for (int j = 0; j < 32; j += 8)
        tile[y + j][x] = in[(size_t)(r0 + y + j) * C + c0 + x];
    __syncthreads();
    #pragma unroll
    for (int j = 0; j < 32; j += 8) {
        int ch = c0 + y + j;
        float v = tile[x][y + j] * alpha[ch] + beta[ch];
        out[(size_t)ch * R + r0 + x] = fmaxf(v, 0.0f);
    }
}

__global__ void prep_bn_kernel(const float* g1, const float* b1, const float* m1, const float* v1,
                               const float* g2, const float* b2, const float* m2, const float* v2)
{
    int i = threadIdx.x + blockIdx.x * blockDim.x;
    if (i < DMODEL) {
        float a = g1[i] * rsqrtf(v1[i] + EPSV);
        g_alpha1[i] = a;
        g_beta1[i]  = b1[i] - m1[i] * a;
    }
    if (i < CIN) {
        float a = g2[i] * rsqrtf(v2[i] + EPSV);
        g_alpha2[i] = a;
        g_beta2[i]  = b2[i] - m2[i] * a;
    }
}

__global__ void bcast_q_kernel(const float* __restrict__ qe, float* __restrict__ Q)
{
    size_t i = (size_t)blockIdx.x * blockDim.x + threadIdx.x;
    size_t per = (size_t)HW * DMODEL;
    if (i < per) {
        float v = qe[i];
        #pragma unroll
        for (int b = 0; b < BATCH; b++)
            Q[(size_t)b * per + i] = v;
    }
}

// Concat per-layer Woff (D x 64) + Wattn (D x 32) -> WOA (D x 96); same for bias
__global__ void concat_woa_kernel(const float* __restrict__ Woff_i, const float* __restrict__ boff_i,
                                  const float* __restrict__ Wattn_i, const float* __restrict__ battn_i)
{
    int i = blockIdx.x * blockDim.x + threadIdx.x;
    if (i < DMODEL * NOA) {
        int r = i / NOA, c = i % NOA;
        g_WOA[i] = (c < 64) ? Woff_i[r * 64 + c] : Wattn_i[r * 32 + (c - 64)];
    }
    if (i < NOA)
        g_bOA[i] = (i < 64) ? boff_i[i] : battn_i[i - 64];
}

// ---------------------------------------------------------------------------
// Deformable sampling with fused per-head softmax.
// One block (256 threads) per query pixel; thread = channel, head = t>>5.
// OA row layout: [offsets: NH*NP*2 = 64][attn logits: NH*NP = 32]
// ---------------------------------------------------------------------------
__device__ __forceinline__ float fetch_val(const float* __restrict__ vb, int xi, int yi, int c)
{
    if (xi < 0 || xi >= WW || yi < 0 || yi >= HH) return 0.0f;
    return vb[((size_t)(yi * WW + xi)) * DMODEL + c];
}

__global__ void __launch_bounds__(256)
deform_sample_kernel(const float* __restrict__ VAL, const float* __restrict__ OA,
                     float* __restrict__ O)
{
    int m = blockIdx.x;
    int b = m >> 12;
    int pix = m & (HW - 1);
    int t = threadIdx.x;
    int head = t >> 5;
    int c = t;

    float rx = ((pix & (WW - 1)) + 0.5f) * (1.0f / WW);
    float ry = ((pix >> 6) + 0.5f) * (1.0f / HH);

    const float* vb   = VAL + (size_t)b * HW * DMODEL;
    const float* offm = OA + (size_t)m * NOA + head * (NP * 2);
    const float* lg   = OA + (size_t)m * NOA + 64 + head * NP;

    // per-head softmax (redundant across the 32 lanes of a head; L1-broadcast)
    float l0 = lg[0], l1 = lg[1], l2 = lg[2], l3 = lg[3];
    float mx = fmaxf(fmaxf(l0, l1), fmaxf(l2, l3));
    float e0 = __expf(l0 - mx), e1 = __expf(l1 - mx);
    float e2 = __expf(l2 - mx), e3 = __expf(l3 - mx);
    float inv = 1.0f / (e0 + e1 + e2 + e3);
    float w[4] = { e0 * inv, e1 * inv, e2 * inv, e3 * inv };

    float acc = 0.0f;
    #pragma unroll
    for (int p = 0; p < NP; p++) {
        float lx = rx + offm[p * 2 + 0] * (1.0f / WW);
        float ly = ry + offm[p * 2 + 1] * (1.0f / HH);
        float gx = lx * WW - 0.5f;
        float gy = ly * HH - 0.5f;
        float fx = floorf(gx), fy = floorf(gy);
        int x0 = (int)fx, y0 = (int)fy;
        float wx = gx - fx, wy = gy - fy;
        float v00 = fetch_val(vb, x0,     y0,     c);
        float v10 = fetch_val(vb, x0 + 1, y0,     c);
        float v01 = fetch_val(vb, x0,     y0 + 1, c);
        float v11 = fetch_val(vb, x0 + 1, y0 + 1, c);
        float s = v00 * (1.f - wx) * (1.f - wy) + v10 * wx * (1.f - wy)
                + v01 * (1.f - wx) * wy         + v11 * wx * wy;
        acc = fmaf(w[p], s, acc);
    }
    O[(size_t)m * DMODEL + c] = acc;
}

// ---------------------------------------------------------------------------
// Residual + LayerNorm (in place on Q)
// ---------------------------------------------------------------------------
__global__ void __launch_bounds__(256)
resid_ln_kernel(float* __restrict__ Q, const float* __restrict__ T,
                const float* __restrict__ gamma, const float* __restrict__ beta)
{
    int row  = blockIdx.x * 8 + (threadIdx.x >> 5);
    int lane = threadIdx.x & 31;
    const float4* qr = (const float4*)(Q + (size_t)row * DMODEL);
    const float4* tr = (const float4*)(T + (size_t)row * DMODEL);

    float x[8];
    float sum = 0.f, sumsq = 0.f;
    #pragma unroll
    for (int i = 0; i < 2; i++) {
        float4 a = qr[lane + i * 32];
        float4 b = tr[lane + i * 32];
        float v0 = a.x + b.x, v1 = a.y + b.y, v2 = a.z + b.z, v3 = a.w + b.w;
        x[i * 4 + 0] = v0; x[i * 4 + 1] = v1; x[i * 4 + 2] = v2; x[i * 4 + 3] = v3;
        sum += v0 + v1 + v2 + v3;
        sumsq += v0 * v0 + v1 * v1 + v2 * v2 + v3 * v3;
    }
    #pragma unroll
    for (int s = 16; s > 0; s >>= 1) {
        sum   += __shfl_xor_sync(0xffffffffu, sum, s);
        sumsq += __shfl_xor_sync(0xffffffffu, sumsq, s);
    }
    float mean = sum * (1.0f / DMODEL);
    float var  = sumsq * (1.0f / DMODEL) - mean * mean;
    float rstd = rsqrtf(var + EPSV);

    float4* qw = (float4*)(Q + (size_t)row * DMODEL);
    #pragma unroll
    for (int i = 0; i < 2; i++) {
        int e = (lane + i * 32) * 4;
        float4 o;
        o.x = (x[i * 4 + 0] - mean) * rstd * gamma[e + 0] + beta[e + 0];
        o.y = (x[i * 4 + 1] - mean) * rstd * gamma[e + 1] + beta[e + 1];
        o.z = (x[i * 4 + 2] - mean) * rstd * gamma[e + 2] + beta[e + 2];
        o.w = (x[i * 4 + 3] - mean) * rstd * gamma[e + 3] + beta[e + 3];
        qw[lane + i * 32] = o;
    }
}

// ---------------------------------------------------------------------------
// Launch
// ---------------------------------------------------------------------------
extern "C" void kernel_launch(void* const* d_in, const int* in_sizes, int n_in,
                              void* d_out, int out_size)
{
    const float* x      = (const float*)d_in[0];
    const float* W_in   = (const float*)d_in[1];
    const float* bn1_g  = (const float*)d_in[2];
    const float* bn1_b  = (const float*)d_in[3];
    const float* bn1_m  = (const float*)d_in[4];
    const float* bn1_v  = (const float*)d_in[5];
    const float* qembed = (const float*)d_in[6];
    const float* Woff   = (const float*)d_in[7];
    const float* boff   = (const float*)d_in[8];
    const float* Wattn  = (const float*)d_in[9];
    const float* battn  = (const float*)d_in[10];
    const float* Wval   = (const float*)d_in[11];
    const float* bval   = (const float*)d_in[12];
    const float* Wo     = (const float*)d_in[13];
    const float* bo     = (const float*)d_in[14];
    const float* ln1_g  = (const float*)d_in[15];
    const float* ln1_b  = (const float*)d_in[16];
    const float* W1     = (const float*)d_in[17];
    const float* b1     = (const float*)d_in[18];
    const float* W2     = (const float*)d_in[19];
    const float* b2     = (const float*)d_in[20];
    const float* ln2_g  = (const float*)d_in[21];
    const float* ln2_b  = (const float*)d_in[22];
    const float* W_out  = (const float*)d_in[23];
    const float* bn2_g  = (const float*)d_in[24];
    const float* bn2_b  = (const float*)d_in[25];
    const float* bn2_m  = (const float*)d_in[26];
    const float* bn2_v  = (const float*)d_in[27];
    float* out = (float*)d_out;

    float *XT, *SRC, *Q, *VAL, *T1, *OA, *H, *WIT, *WOT, *WOA, *bOA;
    float *al1, *be1, *al2, *be2;
    cudaGetSymbolAddress((void**)&XT,  g_XT);
    cudaGetSymbolAddress((void**)&SRC, g_SRC);
    cudaGetSymbolAddress((void**)&Q,   g_Q);
    cudaGetSymbolAddress((void**)&VAL, g_VAL);
    cudaGetSymbolAddress((void**)&T1,  g_T1);
    cudaGetSymbolAddress((void**)&OA,  g_OA);
    cudaGetSymbolAddress((void**)&H,   g_H);
    cudaGetSymbolAddress((void**)&WIT, g_WIT);
    cudaGetSymbolAddress((void**)&WOT, g_WOT);
    cudaGetSymbolAddress((void**)&WOA, g_WOA);
    cudaGetSymbolAddress((void**)&bOA, g_bOA);
    cudaGetSymbolAddress((void**)&al1, g_alpha1);
    cudaGetSymbolAddress((void**)&be1, g_beta1);
    cudaGetSymbolAddress((void**)&al2, g_alpha2);
    cudaGetSymbolAddress((void**)&be2, g_beta2);

    dim3 tb32(32, 8);

    // launches 0..4 (so launch #5 — the ncu capture target — is the proj_in GEMM)
    transpose_kernel<<<dim3(HW / 32, CIN / 32, BATCH), tb32>>>(x, XT, CIN, HW);
    transpose_kernel<<<dim3(CIN / 32, DMODEL / 32, 1), tb32>>>(W_in, WIT, DMODEL, CIN);
    transpose_kernel<<<dim3(DMODEL / 32, CIN / 32, 1), tb32>>>(W_out, WOT, CIN, DMODEL);
    prep_bn_kernel<<<1, 512>>>(bn1_g, bn1_b, bn1_m, bn1_v, bn2_g, bn2_b, bn2_m, bn2_v);
    {
        int per = HW * DMODEL;
        bcast_q_kernel<<<(per + 255) / 256, 256>>>(qembed, Q);
    }

    // launch 5: proj_in GEMM (profiled by ncu -s 5 -c 1)
    gemm_tf32_kernel<<<dim3(DMODEL / 128, MROWS / 128), 256>>>(XT, WIT, SRC,
                                                               MROWS, DMODEL, CIN,
                                                               al1, be1, 1);

    for (int i = 0; i < LNUM; i++) {
        const float* Wval_i  = Wval  + (size_t)i * DMODEL * DMODEL;
        const float* bval_i  = bval  + (size_t)i * DMODEL;
        const float* Woff_i  = Woff  + (size_t)i * DMODEL * (NH * NP * 2);
        const float* boff_i  = boff  + (size_t)i * (NH * NP * 2);
        const float* Wattn_i = Wattn + (size_t)i * DMODEL * (NH * NP);
        const float* battn_i = battn + (size_t)i * (NH * NP);
        const float* Wo_i    = Wo    + (size_t)i * DMODEL * DMODEL;
        const float* bo_i    = bo    + (size_t)i * DMODEL;
        const float* W1_i    = W1    + (size_t)i * DMODEL * DFF;
        const float* b1_i    = b1    + (size_t)i * DFF;
        const float* W2_i    = W2    + (size_t)i * DFF * DMODEL;
        const float* b2_i    = b2    + (size_t)i * DMODEL;

        concat_woa_kernel<<<(DMODEL * NOA + 255) / 256, 256>>>(Woff_i, boff_i,
                                                               Wattn_i, battn_i);

        gemm_tf32_kernel<<<dim3(DMODEL / 128, MROWS / 128), 256>>>(SRC, Wval_i, VAL,
                                                                   MROWS, DMODEL, DMODEL,
                                                                   nullptr, bval_i, 0);
        // merged offsets + attention logits (N=96)
        gemm_tf32_kernel<<<dim3(1, MROWS / 128), 256>>>(Q, WOA, OA,
                                                        MROWS, NOA, DMODEL,
                                                        nullptr, bOA, 0);

        deform_sample_kernel<<<MROWS, 256>>>(VAL, OA, H);

        gemm_tf32_kernel<<<dim3(DMODEL / 128, MROWS / 128), 256>>>(H, Wo_i, T1,
                                                                   MROWS, DMODEL, DMODEL,
                                                                   nullptr, bo_i, 0);
        resid_ln_kernel<<<MROWS / 8, 256>>>(Q, T1, ln1_g + (size_t)i * DMODEL,
                                            ln1_b + (size_t)i * DMODEL);
        gemm_tf32_kernel<<<dim3(DFF / 128, MROWS / 128), 256>>>(Q, W1_i, H,
                                                                MROWS, DFF, DMODEL,
                                                                nullptr, b1_i, 1);
        gemm_tf32_kernel<<<dim3(DMODEL / 128, MROWS / 128), 256>>>(H, W2_i, T1,
                                                                   MROWS, DMODEL, DFF,
                                                                   nullptr, b2_i, 0);
        resid_ln_kernel<<<MROWS / 8, 256>>>(Q, T1, ln2_g + (size_t)i * DMODEL,
                                            ln2_b + (size_t)i * DMODEL);
    }

    gemm_tf32_kernel<<<dim3(CIN / 128, MROWS / 128), 256>>>(Q, WOT, H,
                                                            MROWS, CIN, DMODEL,
                                                            nullptr, nullptr, 0);
    transpose_bn_relu_kernel<<<dim3(CIN / 32, HW / 32, BATCH), tb32>>>(H, out, al2, be2,
                                                                       HW, CIN);
}